// round 15
// baseline (speedup 1.0000x reference)
#include <cuda_runtime.h>
#include <cuda_bf16.h>
#include <math.h>
#include <stdint.h>

#define G 3072
#define P 1024
#define PG 4096          // rows per channel of X
#define M2 8192          // 2 channels stacked
#define ALPHA 0.1f

// ---------------- scratch (device globals; no allocation in kernel_launch) --
__device__ __nv_bfloat16 g_Ascb [(size_t)G * G];   // alpha*softmax, bf16
__device__ __nv_bfloat16 g_AscTb[(size_t)G * G];   // bf16 transpose
__device__ __nv_bfloat16 g_Rb   [(size_t)G * G];   // R = Asc^2 + Asc, bf16
__device__ __nv_bfloat16 g_X2b  [(size_t)M2 * G];  // deinterleaved X, bf16

// ---------------- PTX helpers (generic sm_100 compatible) -------------------
__device__ __forceinline__ uint32_t smem_u32(const void* p) {
    uint32_t a;
    asm("{ .reg .u64 t; cvta.to.shared.u64 t, %1; cvt.u32.u64 %0, t; }"
        : "=r"(a) : "l"(p));
    return a;
}
__device__ __forceinline__ void cp_async16(uint32_t dst, const void* src) {
    asm volatile("cp.async.cg.shared.global [%0], [%1], 16;" :: "r"(dst), "l"(src));
}
#define CP_COMMIT() asm volatile("cp.async.commit_group;" ::: "memory")
#define CP_WAIT(n)  asm volatile("cp.async.wait_group %0;" :: "n"(n) : "memory")

__device__ __forceinline__ void ldsm_x4(uint32_t* r, uint32_t addr) {
    asm volatile("ldmatrix.sync.aligned.m8n8.x4.shared.b16 {%0,%1,%2,%3}, [%4];"
                 : "=r"(r[0]), "=r"(r[1]), "=r"(r[2]), "=r"(r[3]) : "r"(addr));
}
__device__ __forceinline__ void mma_bf16(float* c, const uint32_t* a, const uint32_t* b) {
    asm volatile(
        "mma.sync.aligned.m16n8k16.row.col.f32.bf16.bf16.f32 "
        "{%0,%1,%2,%3}, {%4,%5,%6,%7}, {%8,%9}, {%0,%1,%2,%3};"
        : "+f"(c[0]), "+f"(c[1]), "+f"(c[2]), "+f"(c[3])
        : "r"(a[0]), "r"(a[1]), "r"(a[2]), "r"(a[3]), "r"(b[0]), "r"(b[1]));
}
__device__ __forceinline__ void stg_cs(float* p, float v) {
    asm volatile("st.global.cs.f32 [%0], %1;" :: "l"(p), "f"(v) : "memory");
}

// ---------------- GEMM: D[128x128] = A[128,K] . B[128,K]^T  (bf16 x bf16) ---
// 8 warps: 4 along M x 2 along N, warp tile 32x64. 2 CTAs/SM (128 regs cap).
//   MODE 0: Rb = bf16(D + Addb)                         (R = Asc^2 + Asc)
//   MODE 1: out[(ii*G+col)*2+c] = 0.9*(X[gr,col] + D)    (final, interleave;
//           X via one aligned float4 per output pair; out stored with
//           st.global.cs — write-only, keep it out of L2)
#define TM 128
#define TN 128
#define KCH 64                               // 64 bf16 = 128B rows
#define STAGES 3
#define ATILE_B (TM * KCH * 2)               // 16384
#define STAGE_BYTES (2 * ATILE_B)            // 32768
#define NCHUNK (G / KCH)                     // 48
#define SMEM_DYN (STAGES * STAGE_BYTES)      // 98304

template <int MODE>
__global__ __launch_bounds__(256, 2)
void gemm_mma(const __nv_bfloat16* __restrict__ Aop,
              const __nv_bfloat16* __restrict__ Bop,
              const __nv_bfloat16* __restrict__ Addb,
              void* __restrict__ CoutV,
              const float* __restrict__ pgin,
              const float* __restrict__ ggin) {
    extern __shared__ char smem_raw[];
    const uint32_t sbase = smem_u32(smem_raw);

    const int tid  = threadIdx.x;
    const int lane = tid & 31;
    const int wid  = tid >> 5;
    const int wm   = wid & 3;        // 4 warps along M -> 32 rows each
    const int wn   = wid >> 2;       // 2 warps along N -> 64 cols each
    const int row0 = blockIdx.y * TM;
    const int col0 = blockIdx.x * TN;

    const __nv_bfloat16* arow = Aop + (size_t)row0 * G;
    const __nv_bfloat16* brow = Bop + (size_t)col0 * G;

    // smem per operand tile: [128 rows][64 bf16] = 128B rows, swizzle:
    //   off(r, byte) = r*128 + (byte ^ ((r&7)<<4))
    const int ar    = lane & 15;
    const int abyte = (lane >> 4) << 4;
    const uint32_t amask = (uint32_t)((ar & 7) << 4);
    const uint32_t aoff0 = (uint32_t)((wm * 32 + ar) * 128);
    const uint32_t aoff1 = aoff0 + 16 * 128;
    const int brl   = (lane & 7) | (((lane >> 4) & 1) << 3);
    const int bbyte = ((lane >> 3) & 1) << 4;
    const uint32_t bmask = (uint32_t)((lane & 7) << 4);
    uint32_t boff[4];
#pragma unroll
    for (int ntp = 0; ntp < 4; ntp++)
        boff[ntp] = (uint32_t)((wn * 64 + ntp * 16 + brl) * 128);

    float acc[2][8][4] = {};

    auto load_stage = [&](int stage, int k0) {
        const uint32_t sA = sbase + stage * STAGE_BYTES;
        const uint32_t sB = sA + ATILE_B;
#pragma unroll
        for (int l = 0; l < 4; l++) {
            const int q = tid + (l << 8);
            const int r = q >> 3, sg = q & 7;
            cp_async16(sA + (uint32_t)(r * 128 + ((sg * 16) ^ ((r & 7) << 4))),
                       arow + (size_t)r * G + k0 + sg * 8);
        }
#pragma unroll
        for (int l = 0; l < 4; l++) {
            const int q = tid + (l << 8);
            const int r = q >> 3, sg = q & 7;
            cp_async16(sB + (uint32_t)(r * 128 + ((sg * 16) ^ ((r & 7) << 4))),
                       brow + (size_t)r * G + k0 + sg * 8);
        }
        CP_COMMIT();
    };

    load_stage(0, 0);
    load_stage(1, KCH);

    for (int ch = 0; ch < NCHUNK; ch++) {
        CP_WAIT(STAGES - 2);
        __syncthreads();
        if (ch + STAGES - 1 < NCHUNK)
            load_stage((ch + STAGES - 1) % STAGES, (ch + STAGES - 1) * KCH);
        else
            CP_COMMIT();   // keep wait_group accounting uniform

        const uint32_t sA = sbase + (ch % STAGES) * STAGE_BYTES;
        const uint32_t sB = sA + ATILE_B;
#pragma unroll
        for (int ks = 0; ks < 4; ks++) {       // 4 x k16 steps = k64 chunk
            const uint32_t kb = (uint32_t)(ks * 32);
            uint32_t a0[4], a1[4];
            ldsm_x4(a0, sA + aoff0 + ((kb + abyte) ^ amask));
            ldsm_x4(a1, sA + aoff1 + ((kb + abyte) ^ amask));
            uint32_t b[4][4];
#pragma unroll
            for (int ntp = 0; ntp < 4; ntp++)
                ldsm_x4(b[ntp], sB + boff[ntp] + ((kb + bbyte) ^ bmask));
#pragma unroll
            for (int nt = 0; nt < 8; nt++) {
                const uint32_t* bp = &b[nt >> 1][(nt & 1) * 2];
                mma_bf16(acc[0][nt], a0, bp);
                mma_bf16(acc[1][nt], a1, bp);
            }
        }
    }

    // ---------------- epilogue ------------------------------------------------
    const int rbase = lane >> 2;            // 0..7
    const int cbase = (lane & 3) * 2;       // 0,2,4,6
#pragma unroll
    for (int mt = 0; mt < 2; mt++) {
#pragma unroll
        for (int nt = 0; nt < 8; nt++) {
            const int grow = row0 + wm * 32 + mt * 16 + rbase;
            const int gcol = col0 + wn * 64 + nt * 8 + cbase;
#pragma unroll
            for (int h = 0; h < 2; h++) {
                const int gr = grow + h * 8;
                const float v0 = acc[mt][nt][h * 2 + 0];
                const float v1 = acc[mt][nt][h * 2 + 1];
                if (MODE == 0) {
                    const size_t i0 = (size_t)gr * G + gcol;
                    __nv_bfloat162 ad = *reinterpret_cast<const __nv_bfloat162*>(
                        Addb + i0);
                    __nv_bfloat162 o = __float22bfloat162_rn(
                        make_float2(v0 + __bfloat162float(ad.x),
                                    v1 + __bfloat162float(ad.y)));
                    *reinterpret_cast<__nv_bfloat162*>(
                        (__nv_bfloat16*)CoutV + i0) = o;
                } else {
                    const int c  = gr >> 12;           // channel
                    const int ii = gr & (PG - 1);
                    // one aligned float4 covers both channels of gcol, gcol+1
                    const float4 xq = (ii < P)
                        ? *reinterpret_cast<const float4*>(
                              pgin + ((size_t)ii * G + gcol) * 2)
                        : *reinterpret_cast<const float4*>(
                              ggin + ((size_t)(ii - P) * G + gcol) * 2);
                    const float x0 = c ? xq.y : xq.x;
                    const float x1 = c ? xq.w : xq.z;
                    float* ob = (float*)CoutV + ((size_t)ii * G + gcol) * 2 + c;
                    stg_cs(ob,     0.9f * (x0 + v0));
                    stg_cs(ob + 2, 0.9f * (x1 + v1));
                }
            }
        }
    }
}

// ---- softmax fused with FULL X deinterleave ---------------------------------
// Ascb[i,:] = bf16(alpha * softmax(gg[i,:,1], -inf diag));
// also writes X2b rows for the gg block (global X row P+i, both channels),
// and for blocks i < P additionally deinterleaves the pg row i.
__global__ void softmax_rows_kernel(const float* __restrict__ gg,
                                    const float* __restrict__ pg,
                                    __nv_bfloat16* __restrict__ Ascb,
                                    __nv_bfloat16* __restrict__ X2b) {
    const int i   = blockIdx.x;
    const int tid = threadIdx.x;
    const float2* base2 = reinterpret_cast<const float2*>(gg + (size_t)i * (2 * G));

    __shared__ float rowv[G];
    __shared__ float red[256];

    __nv_bfloat16* x0row = X2b + (size_t)(P + i) * G;
    __nv_bfloat16* x1row = x0row + (size_t)PG * G;

    for (int j = tid; j < G; j += 256) {
        const float2 v = base2[j];
        x0row[j] = __float2bfloat16(v.x);
        x1row[j] = __float2bfloat16(v.y);
        rowv[j] = (j == i) ? -1e30f : v.y;
    }
    __syncthreads();

    float m = -1e30f;
    for (int j = tid; j < G; j += 256) m = fmaxf(m, rowv[j]);
    red[tid] = m;
    __syncthreads();
    for (int s = 128; s > 0; s >>= 1) {
        if (tid < s) red[tid] = fmaxf(red[tid], red[tid + s]);
        __syncthreads();
    }
    const float mx = red[0];
    __syncthreads();

    float sum = 0.0f;
    for (int j = tid; j < G; j += 256) {
        const float e = expf(rowv[j] - mx);
        rowv[j] = e;
        sum += e;
    }
    red[tid] = sum;
    __syncthreads();
    for (int s = 128; s > 0; s >>= 1) {
        if (tid < s) red[tid] += red[tid + s];
        __syncthreads();
    }
    const float inv = ALPHA / red[0];
    __syncthreads();

    for (int j = tid; j < G; j += 256)
        Ascb[(size_t)i * G + j] = __float2bfloat16(rowv[j] * inv);

    // fused pg deinterleave for the first P blocks
    if (i < P) {
        const float2* pbase2 = reinterpret_cast<const float2*>(pg + (size_t)i * (2 * G));
        __nv_bfloat16* p0 = X2b + (size_t)i * G;
        __nv_bfloat16* p1 = p0 + (size_t)PG * G;
        for (int j = tid; j < G; j += 256) {
            const float2 v = pbase2[j];
            p0[j] = __float2bfloat16(v.x);
            p1[j] = __float2bfloat16(v.y);
        }
    }
}

// ---------------- transpose G x G, bf16 -> bf16 ------------------------------
__global__ void transpose_b_k(const __nv_bfloat16* __restrict__ in,
                              __nv_bfloat16* __restrict__ out) {
    __shared__ __nv_bfloat16 t[32][34];
    const int x  = blockIdx.x * 32 + threadIdx.x;
    const int y0 = blockIdx.y * 32;
#pragma unroll
    for (int dy = 0; dy < 32; dy += 8)
        t[threadIdx.y + dy][threadIdx.x] = in[(size_t)(y0 + threadIdx.y + dy) * G + x];
    __syncthreads();
    const int ox = y0 + threadIdx.x;
#pragma unroll
    for (int dy = 0; dy < 32; dy += 8)
        out[(size_t)(blockIdx.x * 32 + threadIdx.y + dy) * G + ox] =
            t[threadIdx.x][threadIdx.y + dy];
}

// ---------------- launcher ---------------------------------------------------
extern "C" void kernel_launch(void* const* d_in, const int* in_sizes, int n_in,
                              void* d_out, int out_size) {
    const float* pg = (const float*)d_in[0];
    const float* gg = (const float*)d_in[1];
    if (in_sizes[0] == G * G * 2) { const float* t = pg; pg = gg; gg = t; }

    __nv_bfloat16 *Ascb, *AscTb, *Rb, *X2b;
    cudaGetSymbolAddress((void**)&Ascb,  g_Ascb);
    cudaGetSymbolAddress((void**)&AscTb, g_AscTb);
    cudaGetSymbolAddress((void**)&Rb,    g_Rb);
    cudaGetSymbolAddress((void**)&X2b,   g_X2b);
    float* out = (float*)d_out;

    cudaFuncSetAttribute(gemm_mma<0>, cudaFuncAttributeMaxDynamicSharedMemorySize, SMEM_DYN);
    cudaFuncSetAttribute(gemm_mma<1>, cudaFuncAttributeMaxDynamicSharedMemorySize, SMEM_DYN);

    // 1. softmax (+ fused full X deinterleave), then AscTb = Ascb^T
    softmax_rows_kernel<<<G, 256>>>(gg, pg, Ascb, X2b);
    transpose_b_k<<<dim3(G / 32, G / 32), dim3(32, 8)>>>(Ascb, AscTb);

    // 2. R = Asc^2 + Asc  (row-major: D[m,n] = sum_k Asc[m,k]Asc[k,n], +Ascb)
    dim3 gh(G / TN, G / TM);                        // (24, 24)
    gemm_mma<0><<<gh, 256, SMEM_DYN>>>(Ascb, AscTb, Ascb, Rb, nullptr, nullptr);

    // 3. out = 0.9 * (X + X @ R^T); exact X read from original inputs
    dim3 gf(G / TN, M2 / TM);                       // (24, 64)
    gemm_mma<1><<<gf, 256, SMEM_DYN>>>(X2b, Rb, nullptr, out, pg, gg);
}

// round 16
// speedup vs baseline: 1.0008x; 1.0008x over previous
#include <cuda_runtime.h>
#include <cuda_bf16.h>
#include <math.h>
#include <stdint.h>

#define G 3072
#define P 1024
#define PG 4096          // rows per channel of X
#define M2 8192          // 2 channels stacked
#define ALPHA 0.1f

// ---------------- scratch (device globals; no allocation in kernel_launch) --
__device__ __nv_bfloat16 g_Ascb [(size_t)G * G];   // alpha*softmax, bf16
__device__ __nv_bfloat16 g_AscTb[(size_t)G * G];   // bf16 transpose
__device__ __nv_bfloat16 g_Rb   [(size_t)G * G];   // R = Asc^2 + Asc, bf16
__device__ __nv_bfloat16 g_X2b  [(size_t)M2 * G];  // deinterleaved X, bf16

// ---------------- PTX helpers (generic sm_100 compatible) -------------------
__device__ __forceinline__ uint32_t smem_u32(const void* p) {
    uint32_t a;
    asm("{ .reg .u64 t; cvta.to.shared.u64 t, %1; cvt.u32.u64 %0, t; }"
        : "=r"(a) : "l"(p));
    return a;
}
__device__ __forceinline__ void cp_async16(uint32_t dst, const void* src) {
    asm volatile("cp.async.cg.shared.global [%0], [%1], 16;" :: "r"(dst), "l"(src));
}
#define CP_COMMIT() asm volatile("cp.async.commit_group;" ::: "memory")
#define CP_WAIT(n)  asm volatile("cp.async.wait_group %0;" :: "n"(n) : "memory")

__device__ __forceinline__ void ldsm_x4(uint32_t* r, uint32_t addr) {
    asm volatile("ldmatrix.sync.aligned.m8n8.x4.shared.b16 {%0,%1,%2,%3}, [%4];"
                 : "=r"(r[0]), "=r"(r[1]), "=r"(r[2]), "=r"(r[3]) : "r"(addr));
}
__device__ __forceinline__ void mma_bf16(float* c, const uint32_t* a, const uint32_t* b) {
    asm volatile(
        "mma.sync.aligned.m16n8k16.row.col.f32.bf16.bf16.f32 "
        "{%0,%1,%2,%3}, {%4,%5,%6,%7}, {%8,%9}, {%0,%1,%2,%3};"
        : "+f"(c[0]), "+f"(c[1]), "+f"(c[2]), "+f"(c[3])
        : "r"(a[0]), "r"(a[1]), "r"(a[2]), "r"(a[3]), "r"(b[0]), "r"(b[1]));
}

// ---------------- GEMM: D[128x128] = A[128,K] . B[128,K]^T  (bf16 x bf16) ---
// 8 warps: 4 along M x 2 along N, warp tile 32x64. 2 CTAs/SM (128 regs cap).
//   MODE 0: Rb = bf16(D + Addb)                         (R = Asc^2 + Asc)
//   MODE 1: out[(ii*G+col)*2+c] = 0.9*(X[gr,col] + D)    (final, interleave;
//           X read exactly from original interleaved fp32 inputs via one
//           aligned float4 per output pair)
#define TM 128
#define TN 128
#define KCH 64                               // 64 bf16 = 128B rows
#define STAGES 3
#define ATILE_B (TM * KCH * 2)               // 16384
#define STAGE_BYTES (2 * ATILE_B)            // 32768
#define NCHUNK (G / KCH)                     // 48
#define SMEM_DYN (STAGES * STAGE_BYTES)      // 98304

template <int MODE>
__global__ __launch_bounds__(256, 2)
void gemm_mma(const __nv_bfloat16* __restrict__ Aop,
              const __nv_bfloat16* __restrict__ Bop,
              const __nv_bfloat16* __restrict__ Addb,
              void* __restrict__ CoutV,
              const float* __restrict__ pgin,
              const float* __restrict__ ggin) {
    extern __shared__ char smem_raw[];
    const uint32_t sbase = smem_u32(smem_raw);

    const int tid  = threadIdx.x;
    const int lane = tid & 31;
    const int wid  = tid >> 5;
    const int wm   = wid & 3;        // 4 warps along M -> 32 rows each
    const int wn   = wid >> 2;       // 2 warps along N -> 64 cols each
    const int row0 = blockIdx.y * TM;
    const int col0 = blockIdx.x * TN;

    const __nv_bfloat16* arow = Aop + (size_t)row0 * G;
    const __nv_bfloat16* brow = Bop + (size_t)col0 * G;

    // smem per operand tile: [128 rows][64 bf16] = 128B rows, swizzle:
    //   off(r, byte) = r*128 + (byte ^ ((r&7)<<4))
    const int ar    = lane & 15;
    const int abyte = (lane >> 4) << 4;
    const uint32_t amask = (uint32_t)((ar & 7) << 4);
    const uint32_t aoff0 = (uint32_t)((wm * 32 + ar) * 128);
    const uint32_t aoff1 = aoff0 + 16 * 128;
    const int brl   = (lane & 7) | (((lane >> 4) & 1) << 3);
    const int bbyte = ((lane >> 3) & 1) << 4;
    const uint32_t bmask = (uint32_t)((lane & 7) << 4);
    uint32_t boff[4];
#pragma unroll
    for (int ntp = 0; ntp < 4; ntp++)
        boff[ntp] = (uint32_t)((wn * 64 + ntp * 16 + brl) * 128);

    float acc[2][8][4] = {};

    auto load_stage = [&](int stage, int k0) {
        const uint32_t sA = sbase + stage * STAGE_BYTES;
        const uint32_t sB = sA + ATILE_B;
#pragma unroll
        for (int l = 0; l < 4; l++) {
            const int q = tid + (l << 8);
            const int r = q >> 3, sg = q & 7;
            cp_async16(sA + (uint32_t)(r * 128 + ((sg * 16) ^ ((r & 7) << 4))),
                       arow + (size_t)r * G + k0 + sg * 8);
        }
#pragma unroll
        for (int l = 0; l < 4; l++) {
            const int q = tid + (l << 8);
            const int r = q >> 3, sg = q & 7;
            cp_async16(sB + (uint32_t)(r * 128 + ((sg * 16) ^ ((r & 7) << 4))),
                       brow + (size_t)r * G + k0 + sg * 8);
        }
        CP_COMMIT();
    };

    load_stage(0, 0);
    load_stage(1, KCH);

    for (int ch = 0; ch < NCHUNK; ch++) {
        CP_WAIT(STAGES - 2);
        __syncthreads();
        if (ch + STAGES - 1 < NCHUNK)
            load_stage((ch + STAGES - 1) % STAGES, (ch + STAGES - 1) * KCH);
        else
            CP_COMMIT();   // keep wait_group accounting uniform

        const uint32_t sA = sbase + (ch % STAGES) * STAGE_BYTES;
        const uint32_t sB = sA + ATILE_B;
#pragma unroll
        for (int ks = 0; ks < 4; ks++) {       // 4 x k16 steps = k64 chunk
            const uint32_t kb = (uint32_t)(ks * 32);
            uint32_t a0[4], a1[4];
            ldsm_x4(a0, sA + aoff0 + ((kb + abyte) ^ amask));
            ldsm_x4(a1, sA + aoff1 + ((kb + abyte) ^ amask));
            uint32_t b[4][4];
#pragma unroll
            for (int ntp = 0; ntp < 4; ntp++)
                ldsm_x4(b[ntp], sB + boff[ntp] + ((kb + bbyte) ^ bmask));
#pragma unroll
            for (int nt = 0; nt < 8; nt++) {
                const uint32_t* bp = &b[nt >> 1][(nt & 1) * 2];
                mma_bf16(acc[0][nt], a0, bp);
                mma_bf16(acc[1][nt], a1, bp);
            }
        }
    }

    // ---------------- epilogue ------------------------------------------------
    const int rbase = lane >> 2;            // 0..7
    const int cbase = (lane & 3) * 2;       // 0,2,4,6
#pragma unroll
    for (int mt = 0; mt < 2; mt++) {
#pragma unroll
        for (int nt = 0; nt < 8; nt++) {
            const int grow = row0 + wm * 32 + mt * 16 + rbase;
            const int gcol = col0 + wn * 64 + nt * 8 + cbase;
#pragma unroll
            for (int h = 0; h < 2; h++) {
                const int gr = grow + h * 8;
                const float v0 = acc[mt][nt][h * 2 + 0];
                const float v1 = acc[mt][nt][h * 2 + 1];
                if (MODE == 0) {
                    const size_t i0 = (size_t)gr * G + gcol;
                    __nv_bfloat162 ad = *reinterpret_cast<const __nv_bfloat162*>(
                        Addb + i0);
                    __nv_bfloat162 o = __float22bfloat162_rn(
                        make_float2(v0 + __bfloat162float(ad.x),
                                    v1 + __bfloat162float(ad.y)));
                    *reinterpret_cast<__nv_bfloat162*>(
                        (__nv_bfloat16*)CoutV + i0) = o;
                } else {
                    const int c  = gr >> 12;           // channel
                    const int ii = gr & (PG - 1);
                    // one aligned float4 covers both channels of gcol, gcol+1;
                    // elements c and 2+c are X[ii,gcol,c], X[ii,gcol+1,c]
                    const float4 xq = (ii < P)
                        ? *reinterpret_cast<const float4*>(
                              pgin + ((size_t)ii * G + gcol) * 2)
                        : *reinterpret_cast<const float4*>(
                              ggin + ((size_t)(ii - P) * G + gcol) * 2);
                    const float x0 = c ? xq.y : xq.x;
                    const float x1 = c ? xq.w : xq.z;
                    float* ob = (float*)CoutV + ((size_t)ii * G + gcol) * 2 + c;
                    ob[0] = 0.9f * (x0 + v0);
                    ob[2] = 0.9f * (x1 + v1);
                }
            }
        }
    }
}

// ---- softmax fused with FULL X deinterleave ---------------------------------
// Ascb[i,:] = bf16(alpha * softmax(gg[i,:,1], -inf diag));
// also writes X2b rows for the gg block (global X row P+i, both channels),
// and for blocks i < P additionally deinterleaves the pg row i.
__global__ void softmax_rows_kernel(const float* __restrict__ gg,
                                    const float* __restrict__ pg,
                                    __nv_bfloat16* __restrict__ Ascb,
                                    __nv_bfloat16* __restrict__ X2b) {
    const int i   = blockIdx.x;
    const int tid = threadIdx.x;
    const float2* base2 = reinterpret_cast<const float2*>(gg + (size_t)i * (2 * G));

    __shared__ float rowv[G];
    __shared__ float red[256];

    __nv_bfloat16* x0row = X2b + (size_t)(P + i) * G;
    __nv_bfloat16* x1row = x0row + (size_t)PG * G;

    for (int j = tid; j < G; j += 256) {
        const float2 v = base2[j];
        x0row[j] = __float2bfloat16(v.x);
        x1row[j] = __float2bfloat16(v.y);
        rowv[j] = (j == i) ? -1e30f : v.y;
    }
    __syncthreads();

    float m = -1e30f;
    for (int j = tid; j < G; j += 256) m = fmaxf(m, rowv[j]);
    red[tid] = m;
    __syncthreads();
    for (int s = 128; s > 0; s >>= 1) {
        if (tid < s) red[tid] = fmaxf(red[tid], red[tid + s]);
        __syncthreads();
    }
    const float mx = red[0];
    __syncthreads();

    float sum = 0.0f;
    for (int j = tid; j < G; j += 256) {
        const float e = expf(rowv[j] - mx);
        rowv[j] = e;
        sum += e;
    }
    red[tid] = sum;
    __syncthreads();
    for (int s = 128; s > 0; s >>= 1) {
        if (tid < s) red[tid] += red[tid + s];
        __syncthreads();
    }
    const float inv = ALPHA / red[0];
    __syncthreads();

    for (int j = tid; j < G; j += 256)
        Ascb[(size_t)i * G + j] = __float2bfloat16(rowv[j] * inv);

    // fused pg deinterleave for the first P blocks
    if (i < P) {
        const float2* pbase2 = reinterpret_cast<const float2*>(pg + (size_t)i * (2 * G));
        __nv_bfloat16* p0 = X2b + (size_t)i * G;
        __nv_bfloat16* p1 = p0 + (size_t)PG * G;
        for (int j = tid; j < G; j += 256) {
            const float2 v = pbase2[j];
            p0[j] = __float2bfloat16(v.x);
            p1[j] = __float2bfloat16(v.y);
        }
    }
}

// ---------------- transpose G x G, bf16 -> bf16 ------------------------------
__global__ void transpose_b_k(const __nv_bfloat16* __restrict__ in,
                              __nv_bfloat16* __restrict__ out) {
    __shared__ __nv_bfloat16 t[32][34];
    const int x  = blockIdx.x * 32 + threadIdx.x;
    const int y0 = blockIdx.y * 32;
#pragma unroll
    for (int dy = 0; dy < 32; dy += 8)
        t[threadIdx.y + dy][threadIdx.x] = in[(size_t)(y0 + threadIdx.y + dy) * G + x];
    __syncthreads();
    const int ox = y0 + threadIdx.x;
#pragma unroll
    for (int dy = 0; dy < 32; dy += 8)
        out[(size_t)(blockIdx.x * 32 + threadIdx.y + dy) * G + ox] =
            t[threadIdx.x][threadIdx.y + dy];
}

// ---------------- launcher ---------------------------------------------------
extern "C" void kernel_launch(void* const* d_in, const int* in_sizes, int n_in,
                              void* d_out, int out_size) {
    const float* pg = (const float*)d_in[0];
    const float* gg = (const float*)d_in[1];
    if (in_sizes[0] == G * G * 2) { const float* t = pg; pg = gg; gg = t; }

    __nv_bfloat16 *Ascb, *AscTb, *Rb, *X2b;
    cudaGetSymbolAddress((void**)&Ascb,  g_Ascb);
    cudaGetSymbolAddress((void**)&AscTb, g_AscTb);
    cudaGetSymbolAddress((void**)&Rb,    g_Rb);
    cudaGetSymbolAddress((void**)&X2b,   g_X2b);
    float* out = (float*)d_out;

    cudaFuncSetAttribute(gemm_mma<0>, cudaFuncAttributeMaxDynamicSharedMemorySize, SMEM_DYN);
    cudaFuncSetAttribute(gemm_mma<1>, cudaFuncAttributeMaxDynamicSharedMemorySize, SMEM_DYN);

    // 1. softmax (+ fused full X deinterleave), then AscTb = Ascb^T
    softmax_rows_kernel<<<G, 256>>>(gg, pg, Ascb, X2b);
    transpose_b_k<<<dim3(G / 32, G / 32), dim3(32, 8)>>>(Ascb, AscTb);

    // 2. R = Asc^2 + Asc  (row-major: D[m,n] = sum_k Asc[m,k]Asc[k,n], +Ascb)
    dim3 gh(G / TN, G / TM);                        // (24, 24)
    gemm_mma<0><<<gh, 256, SMEM_DYN>>>(Ascb, AscTb, Ascb, Rb, nullptr, nullptr);

    // 3. out = 0.9 * (X + X @ R^T); exact X read from original inputs
    dim3 gf(G / TN, M2 / TM);                       // (24, 64)
    gemm_mma<1><<<gf, 256, SMEM_DYN>>>(X2b, Rb, nullptr, out, pg, gg);
}